// round 13
// baseline (speedup 1.0000x reference)
#include <cuda_runtime.h>
#include <cuda_fp16.h>
#include <cstdint>
#include <cmath>

#define B_ 64
#define T_ 1024
#define D_ 512
#define H_ 768
#define G4 3072   // 4*H
#define OW 1536   // 2*H
#define NBD 64    // column blocks per direction
#define NTILE 48  // z-columns per block

// ---------------- scratch (device globals) ----------------------------------
__device__ __half   g_xzh[2][(size_t)T_ * B_ * G4];  // gate-permuted input proj, fp16
__device__ __half   g_xh[(size_t)B_ * T_ * D_];      // x converted to fp16
__device__ __half   g_Wph[2][(size_t)G4 * D_];       // permuted W, transposed [n][k]
__device__ __half   g_Ut[2][(size_t)G4 * H_];        // permuted U, transposed [n][k]
__device__ __half   g_h[2][2][B_ * H_];              // [dir][phase], fp16
__device__ unsigned g_bar_cnt[2][32];                // padded: one line per dir
__device__ unsigned g_bar_gen[2][32];

// ---------------- helpers --------------------------------------------------
__device__ __forceinline__ void mma_f16(float* c, const uint32_t* a,
                                        uint32_t b0, uint32_t b1) {
    asm volatile(
        "mma.sync.aligned.m16n8k16.row.col.f32.f16.f16.f32 "
        "{%0,%1,%2,%3}, {%4,%5,%6,%7}, {%8,%9}, {%0,%1,%2,%3};"
        : "+f"(c[0]), "+f"(c[1]), "+f"(c[2]), "+f"(c[3])
        : "r"(a[0]), "r"(a[1]), "r"(a[2]), "r"(a[3]), "r"(b0), "r"(b1));
}
// fp16-accumulate variant: D,C are 2 packed half2 regs (full-rate HMMA path)
__device__ __forceinline__ void mma_f16acc(uint32_t* c, const uint32_t* a,
                                           uint32_t b0, uint32_t b1) {
    asm volatile(
        "mma.sync.aligned.m16n8k16.row.col.f16.f16.f16.f16 "
        "{%0,%1}, {%2,%3,%4,%5}, {%6,%7}, {%0,%1};"
        : "+r"(c[0]), "+r"(c[1])
        : "r"(a[0]), "r"(a[1]), "r"(a[2]), "r"(a[3]), "r"(b0), "r"(b1));
}
__device__ __forceinline__ void ldsm_x4(uint32_t* r, uint32_t saddr) {
    asm volatile("ldmatrix.sync.aligned.m8n8.x4.shared.b16 {%0,%1,%2,%3}, [%4];"
        : "=r"(r[0]), "=r"(r[1]), "=r"(r[2]), "=r"(r[3]) : "r"(saddr));
}
__device__ __forceinline__ void ldsm_x2(uint32_t* r, uint32_t saddr) {
    asm volatile("ldmatrix.sync.aligned.m8n8.x2.shared.b16 {%0,%1}, [%2];"
        : "=r"(r[0]), "=r"(r[1]) : "r"(saddr));
}
__device__ __forceinline__ void cp_async16(uint32_t smem_u32, const void* gptr) {
    asm volatile("cp.async.cg.shared.global [%0], [%1], 16;"
                 :: "r"(smem_u32), "l"(gptr));
}
#define CP_COMMIT() asm volatile("cp.async.commit_group;")
#define CP_WAIT2()  asm volatile("cp.async.wait_group 2;")

__device__ __forceinline__ float tanhf_(float x) {
    float r; asm("tanh.approx.f32 %0, %1;" : "=f"(r) : "f"(x)); return r;
}
__device__ __forceinline__ float sigm_(float x) {
    return fmaf(0.5f, tanhf_(0.5f * x), 0.5f);
}

// ---------------- prep kernels ---------------------------------------------
__global__ void prep_x(const float* __restrict__ x) {
    size_t i = (size_t)blockIdx.x * 256 + threadIdx.x;
    if (i >= (size_t)B_ * T_ * D_) return;
    g_xh[i] = __float2half(x[i]);
}

__global__ void prep_w(const float* __restrict__ Wf, const float* __restrict__ Wb) {
    int i = blockIdx.x * 256 + threadIdx.x;
    if (i >= G4 * D_) return;
    int n = i / D_;
    int k = i % D_;
    int src = k * G4 + (n & 3) * H_ + (n >> 2);
    g_Wph[0][i] = __float2half(Wf[src]);
    g_Wph[1][i] = __float2half(Wb[src]);
}

__global__ void prep_u(const float* __restrict__ Uf, const float* __restrict__ Ub) {
    int i = blockIdx.x * 256 + threadIdx.x;
    if (i >= H_ * G4) return;
    int n = i % G4;
    int k = i / G4;
    int src = k * G4 + (n & 3) * H_ + (n >> 2);
    g_Ut[0][(size_t)n * H_ + k] = __float2half(Uf[src]);
    g_Ut[1][(size_t)n * H_ + k] = __float2half(Ub[src]);
}

__global__ void prep_state() {
    int i = blockIdx.x * 256 + threadIdx.x;
    if (i >= B_ * H_) return;
    g_h[0][0][i] = __half(0.0f); g_h[0][1][i] = __half(0.0f);
    g_h[1][0][i] = __half(0.0f); g_h[1][1][i] = __half(0.0f);
}

// ---------------- input projection GEMM (fp16 in, fp16 out) -----------------
#define PJ_PAD 24

__global__ __launch_bounds__(256) void proj_kernel(const float* __restrict__ bfv,
                                                   const float* __restrict__ bbv) {
    __shared__ __half As[128][PJ_PAD];
    __shared__ __half Bs[128][PJ_PAD];

    const int dir = blockIdx.z;
    const __half* __restrict__ Wp = g_Wph[dir];
    const __half* __restrict__ xh = g_xh;
    const float* __restrict__ bias = dir ? bbv : bfv;
    const int row0 = blockIdx.x * 128;
    const int n0   = blockIdx.y * 128;
    const int tid  = threadIdx.x;
    const int lane = tid & 31;
    const int warp = tid >> 5;
    const int wm = warp & 1;
    const int wn = warp >> 1;

    const uint32_t As_base = (uint32_t)__cvta_generic_to_shared(&As[0][0]);
    const uint32_t Bs_base = (uint32_t)__cvta_generic_to_shared(&Bs[0][0]);
    const int lrow = lane & 15;
    const int lkc  = (lane >> 4) * 8;

    float acc[4][4][4];
    #pragma unroll
    for (int mi = 0; mi < 4; mi++)
        #pragma unroll
        for (int ni = 0; ni < 4; ni++)
            #pragma unroll
            for (int e = 0; e < 4; e++) acc[mi][ni][e] = 0.0f;

    for (int k0 = 0; k0 < D_; k0 += 16) {
        {
            int row = tid >> 1;
            int c8 = (tid & 1) * 8;
            uint4 v = *(const uint4*)(xh + (size_t)(row0 + row) * D_ + k0 + c8);
            *(uint4*)&As[row][c8] = v;
        }
        {
            int row = tid >> 1;
            int c8 = (tid & 1) * 8;
            uint4 v = *(const uint4*)(Wp + (size_t)(n0 + row) * D_ + k0 + c8);
            *(uint4*)&Bs[row][c8] = v;
        }
        __syncthreads();

        uint32_t bfr[4][2];
        #pragma unroll
        for (int np = 0; np < 2; np++) {
            uint32_t b4[4];
            ldsm_x4(b4, Bs_base + (uint32_t)(((wn * 32 + np * 16 + lrow) * PJ_PAD + lkc) * 2));
            bfr[np * 2 + 0][0] = b4[0]; bfr[np * 2 + 1][0] = b4[1];
            bfr[np * 2 + 0][1] = b4[2]; bfr[np * 2 + 1][1] = b4[3];
        }
        #pragma unroll
        for (int mi = 0; mi < 4; mi++) {
            uint32_t af[4];
            ldsm_x4(af, As_base + (uint32_t)(((wm * 64 + mi * 16 + lrow) * PJ_PAD + lkc) * 2));
            #pragma unroll
            for (int ni = 0; ni < 4; ni++)
                mma_f16(acc[mi][ni], af, bfr[ni][0], bfr[ni][1]);
        }
        __syncthreads();
    }

    #pragma unroll
    for (int mi = 0; mi < 4; mi++) {
        #pragma unroll
        for (int ni = 0; ni < 4; ni++) {
            int rl = wm * 64 + mi * 16 + (lane >> 2);
            int cl = wn * 32 + ni * 8 + 2 * (lane & 3);
            #pragma unroll
            for (int p = 0; p < 2; p++) {
                int rr = rl + p * 8;
                int grow = row0 + rr;
                int b = grow >> 10;
                int t = grow & (T_ - 1);
                int n = n0 + cl;
                float v0 = acc[mi][ni][2 * p + 0] + __ldg(&bias[(n & 3) * H_ + (n >> 2)]);
                float v1 = acc[mi][ni][2 * p + 1] + __ldg(&bias[((n + 1) & 3) * H_ + ((n + 1) >> 2)]);
                *(__half2*)&g_xzh[dir][((size_t)t * B_ + b) * G4 + n] =
                    __floats2half2_rn(v0, v1);
            }
        }
    }
}

// ---------------- persistent recurrent kernel (R12 + fp16 accumulators) -----
#define UT_PAD   776                 // halves per Ut row
#define A_PAD    72                  // halves per A-stage row
#define SMEM_UT_HALVES (NTILE * UT_PAD)
#define SMEM_A_HALVES  (4 * 64 * A_PAD)
#define SMEM_BYTES 118784   // pad to 116KB: forces occupancy 1 -> 1 block/SM

__global__ __launch_bounds__(256, 1) void rnn_persistent(float* __restrict__ out) {
    extern __shared__ char smem_raw[];
    __half* Us = (__half*)smem_raw;                              // [48][UT_PAD]
    __half* Ah = (__half*)(smem_raw + SMEM_UT_HALVES * 2);       // 4 stages [64][A_PAD]

    const int dir = blockIdx.y;
    const int n0  = blockIdx.x * NTILE;
    const int tid = threadIdx.x;
    const int lane = tid & 31;
    const int warp = tid >> 5;
    const int wm = warp & 3;     // 4 m-groups (batch rows)
    const int wn = warp >> 2;    // 2 n-groups (24 z-cols each)

    const __half* __restrict__ xzd = g_xzh[dir];

    // ---- load Ut tile once ----
    {
        const __half* src = g_Ut[dir] + (size_t)n0 * H_;
        for (int idx = tid; idx < NTILE * 96; idx += 256) {
            int n = idx / 96, ch = idx % 96;
            uint4 v = *(const uint4*)(src + (size_t)n * H_ + ch * 8);
            *(uint4*)(Us + n * UT_PAD + ch * 8) = v;
        }
    }
    __syncthreads();

    // cp.async geometry (64 rows x 64 halves per stage)
    const int ar   = tid >> 2;
    const int ac16 = (tid & 3) * 16;
    const uint32_t a_dst_base =
        (uint32_t)__cvta_generic_to_shared(Ah + ar * A_PAD + ac16);
    const uint32_t a_stage_stride = 64 * A_PAD * 2;

    // ldmatrix geometry
    const int lrow = lane & 15;
    const int lkc  = (lane >> 4) * 8;
    const int l15  = lane & 15;
    const uint32_t Ah_base = (uint32_t)__cvta_generic_to_shared(Ah);
    const uint32_t Us_base = (uint32_t)__cvta_generic_to_shared(Us);
    const uint32_t a_frag0 = Ah_base + (uint32_t)(((wm * 16 + lrow) * A_PAD + lkc) * 2);
    const uint32_t u4_base = Us_base + (uint32_t)(((wn * 24 + lrow) * UT_PAD + lkc) * 2);
    const uint32_t u2_base = Us_base + (uint32_t)(((wn * 24 + 16 + (l15 & 7)) * UT_PAD
                                                   + (l15 >> 3) * 8) * 2);

    // epilogue geometry
    const int c0 = wn * 24 + 2 * (lane & 3);
    const int jg = (n0 >> 2) + wn * 6 + ((lane & 3) >> 1);
    const bool store_lane = ((lane & 1) == 0);

    float creg[2][3];
    #pragma unroll
    for (int p = 0; p < 2; p++)
        #pragma unroll
        for (int ni = 0; ni < 3; ni++) creg[p][ni] = 0.0f;

    unsigned bar_gen_seen;
    asm volatile("ld.relaxed.gpu.u32 %0, [%1];"
                 : "=r"(bar_gen_seen) : "l"(&g_bar_gen[dir][0]));

    __half2 xzr[2][3];
    {
        const int tt0 = dir ? (T_ - 1) : 0;
        const __half* xb = xzd + (size_t)tt0 * (B_ * G4) + n0 + c0;
        #pragma unroll
        for (int p = 0; p < 2; p++) {
            int b = wm * 16 + (lane >> 2) + 8 * p;
            #pragma unroll
            for (int ni = 0; ni < 3; ni++)
                xzr[p][ni] = __ldcs((const __half2*)(xb + (size_t)b * G4 + ni * 8));
        }
    }

    for (int t = 0; t < T_; t++) {
        const __half* __restrict__ hp = g_h[dir][t & 1];
        __half* __restrict__ hnext = g_h[dir][(t + 1) & 1];
        const int tt = dir ? (T_ - 1 - t) : t;

        // fp16 accumulators, two independent banks (even/odd ks)
        uint32_t acch[3][2], acc2h[3][2];
        #pragma unroll
        for (int ni = 0; ni < 3; ni++) {
            acch[ni][0] = 0u; acch[ni][1] = 0u;
            acc2h[ni][0] = 0u; acc2h[ni][1] = 0u;
        }

        const char* hsrc = (const char*)(hp + (size_t)ar * H_ + ac16);

        #pragma unroll
        for (int s = 0; s < 3; s++) {
            cp_async16(a_dst_base + s * a_stage_stride, hsrc + (size_t)s * 128);
            cp_async16(a_dst_base + s * a_stage_stride + 16, hsrc + (size_t)s * 128 + 16);
            CP_COMMIT();
        }

        for (int i = 0; i < 12; i++) {     // k64 stages
            CP_WAIT2();
            __syncthreads();
            if (i < 9) {
                uint32_t d = a_dst_base + ((i + 3) & 3) * a_stage_stride;
                const char* s = hsrc + (size_t)(i + 3) * 128;
                cp_async16(d, s);
                cp_async16(d + 16, s + 16);
            }
            CP_COMMIT();

            const uint32_t a_st = a_frag0 + (uint32_t)(i & 3) * a_stage_stride;
            const uint32_t kb   = (uint32_t)(i * 128);   // i*64 halves in bytes
            #pragma unroll
            for (int ks = 0; ks < 4; ks++) {
                uint32_t b4[4], bx[2], af[4];
                ldsm_x4(b4, u4_base + kb + ks * 32);
                ldsm_x2(bx, u2_base + kb + ks * 32);
                ldsm_x4(af, a_st + ks * 32);
                uint32_t (*A)[2] = (ks & 1) ? acc2h : acch;
                mma_f16acc(A[0], af, b4[0], b4[2]);
                mma_f16acc(A[1], af, b4[1], b4[3]);
                mma_f16acc(A[2], af, bx[0], bx[1]);
            }
        }

        // merge banks in fp32
        float acc[3][4];
        #pragma unroll
        for (int ni = 0; ni < 3; ni++) {
            float2 a01 = __half22float2(*(__half2*)&acch[ni][0]);
            float2 a23 = __half22float2(*(__half2*)&acch[ni][1]);
            float2 b01 = __half22float2(*(__half2*)&acc2h[ni][0]);
            float2 b23 = __half22float2(*(__half2*)&acc2h[ni][1]);
            acc[ni][0] = a01.x + b01.x;
            acc[ni][1] = a01.y + b01.y;
            acc[ni][2] = a23.x + b23.x;
            acc[ni][3] = a23.y + b23.y;
        }

        // ---- epilogue in fragment layout ----
        #pragma unroll
        for (int p = 0; p < 2; p++) {
            int b = wm * 16 + (lane >> 2) + 8 * p;
            #pragma unroll
            for (int ni = 0; ni < 3; ni++) {
                float2 xf = __half22float2(xzr[p][ni]);
                float a0 = acc[ni][2 * p + 0] + xf.x;
                float a1 = acc[ni][2 * p + 1] + xf.y;
                float b0 = __shfl_xor_sync(0xffffffffu, a0, 1);
                float b1 = __shfl_xor_sync(0xffffffffu, a1, 1);
                bool oddl = lane & 1;
                float zi = oddl ? b0 : a0;
                float zf = oddl ? b1 : a1;
                float zg = oddl ? a0 : b0;
                float zo = oddl ? a1 : b1;

                float ig = sigm_(zi);
                float fg = sigm_(zf);
                float og = sigm_(zo);
                float c = fg * creg[p][ni] + ig * tanhf_(zg);
                creg[p][ni] = c;
                float h = og * tanhf_(c);

                if (store_lane) {
                    int j = jg + 2 * ni;
                    hnext[b * H_ + j] = __float2half(h);
                    out[((size_t)b * T_ + tt) * OW + dir * H_ + j] = h;
                }
            }
        }

        // xz prefetch for t+1
        if (t + 1 < T_) {
            const int tn = dir ? (T_ - 2 - t) : (t + 1);
            const __half* xb = xzd + (size_t)tn * (B_ * G4) + n0 + c0;
            #pragma unroll
            for (int p = 0; p < 2; p++) {
                int b = wm * 16 + (lane >> 2) + 8 * p;
                #pragma unroll
                for (int ni = 0; ni < 3; ni++)
                    xzr[p][ni] = __ldcs((const __half2*)(xb + (size_t)b * G4 + ni * 8));
            }
        }

        // ---- per-direction flat grid barrier (acq_rel atomics) ----
        __syncthreads();
        if (tid == 0) {
            unsigned old;
            asm volatile("atom.acq_rel.gpu.add.u32 %0, [%1], 1;"
                         : "=r"(old) : "l"(&g_bar_cnt[dir][0]) : "memory");
            if (old == NBD - 1) {
                asm volatile("st.relaxed.gpu.u32 [%0], 0;"
                             :: "l"(&g_bar_cnt[dir][0]) : "memory");
                asm volatile("st.release.gpu.u32 [%0], %1;"
                             :: "l"(&g_bar_gen[dir][0]), "r"(bar_gen_seen + 1) : "memory");
            } else {
                unsigned g;
                do {
                    asm volatile("ld.acquire.gpu.u32 %0, [%1];"
                                 : "=r"(g) : "l"(&g_bar_gen[dir][0]) : "memory");
                } while (g == bar_gen_seen);
            }
        }
        bar_gen_seen++;
        __syncthreads();
    }
}

// ---------------- launch ----------------------------------------------------
extern "C" void kernel_launch(void* const* d_in, const int* in_sizes, int n_in,
                              void* d_out, int out_size) {
    (void)in_sizes; (void)n_in; (void)out_size;
    const float* x  = (const float*)d_in[0];
    const float* Wf = (const float*)d_in[1];
    const float* Uf = (const float*)d_in[2];
    const float* bf = (const float*)d_in[3];
    const float* Wb = (const float*)d_in[4];
    const float* Ub = (const float*)d_in[5];
    const float* bb = (const float*)d_in[6];
    float* out = (float*)d_out;

    cudaFuncSetAttribute(rnn_persistent,
                         cudaFuncAttributeMaxDynamicSharedMemorySize, SMEM_BYTES);

    prep_x<<<(int)(((size_t)B_ * T_ * D_ + 255) / 256), 256>>>(x);
    prep_w<<<(G4 * D_ + 255) / 256, 256>>>(Wf, Wb);
    prep_u<<<(H_ * G4 + 255) / 256, 256>>>(Uf, Ub);
    prep_state<<<(B_ * H_ + 255) / 256, 256>>>();

    proj_kernel<<<dim3(512, 24, 2), 256>>>(bf, bb);

    rnn_persistent<<<dim3(NBD, 2), 256, SMEM_BYTES>>>(out);
}

// round 14
// speedup vs baseline: 1.0215x; 1.0215x over previous
#include <cuda_runtime.h>
#include <cuda_fp16.h>
#include <cstdint>
#include <cmath>

#define B_ 64
#define T_ 1024
#define D_ 512
#define H_ 768
#define G4 3072   // 4*H
#define OW 1536   // 2*H
#define NBD 64    // column blocks per direction
#define NTILE 48  // z-columns per block

// ---------------- scratch (device globals) ----------------------------------
__device__ __half   g_xzh[2][(size_t)T_ * B_ * G4];  // gate-permuted input proj, fp16
__device__ __half   g_xh[(size_t)B_ * T_ * D_];      // x converted to fp16
__device__ __half   g_Wph[2][(size_t)G4 * D_];       // permuted W, transposed [n][k]
__device__ __half   g_Ut[2][(size_t)G4 * H_];        // permuted U, transposed [n][k]
__device__ __half   g_h[2][2][B_ * H_];              // [dir][phase], fp16
__device__ unsigned g_bar_cnt[2][32];                // padded: one line per dir
__device__ unsigned g_bar_gen[2][32];

// ---------------- helpers --------------------------------------------------
__device__ __forceinline__ void mma_f16(float* c, const uint32_t* a,
                                        uint32_t b0, uint32_t b1) {
    asm volatile(
        "mma.sync.aligned.m16n8k16.row.col.f32.f16.f16.f32 "
        "{%0,%1,%2,%3}, {%4,%5,%6,%7}, {%8,%9}, {%0,%1,%2,%3};"
        : "+f"(c[0]), "+f"(c[1]), "+f"(c[2]), "+f"(c[3])
        : "r"(a[0]), "r"(a[1]), "r"(a[2]), "r"(a[3]), "r"(b0), "r"(b1));
}
__device__ __forceinline__ void ldsm_x4(uint32_t* r, uint32_t saddr) {
    asm volatile("ldmatrix.sync.aligned.m8n8.x4.shared.b16 {%0,%1,%2,%3}, [%4];"
        : "=r"(r[0]), "=r"(r[1]), "=r"(r[2]), "=r"(r[3]) : "r"(saddr));
}
__device__ __forceinline__ void ldsm_x2(uint32_t* r, uint32_t saddr) {
    asm volatile("ldmatrix.sync.aligned.m8n8.x2.shared.b16 {%0,%1}, [%2];"
        : "=r"(r[0]), "=r"(r[1]) : "r"(saddr));
}
__device__ __forceinline__ void cp_async16(uint32_t smem_u32, const void* gptr) {
    asm volatile("cp.async.cg.shared.global [%0], [%1], 16;"
                 :: "r"(smem_u32), "l"(gptr));
}
#define CP_COMMIT() asm volatile("cp.async.commit_group;")
#define CP_WAIT2()  asm volatile("cp.async.wait_group 2;")

__device__ __forceinline__ float tanhf_(float x) {
    float r; asm("tanh.approx.f32 %0, %1;" : "=f"(r) : "f"(x)); return r;
}
__device__ __forceinline__ float sigm_(float x) {
    return fmaf(0.5f, tanhf_(0.5f * x), 0.5f);
}

// ---------------- prep kernels ---------------------------------------------
__global__ void prep_x(const float* __restrict__ x) {
    size_t i = (size_t)blockIdx.x * 256 + threadIdx.x;
    if (i >= (size_t)B_ * T_ * D_) return;
    g_xh[i] = __float2half(x[i]);
}

__global__ void prep_w(const float* __restrict__ Wf, const float* __restrict__ Wb) {
    int i = blockIdx.x * 256 + threadIdx.x;
    if (i >= G4 * D_) return;
    int n = i / D_;
    int k = i % D_;
    int src = k * G4 + (n & 3) * H_ + (n >> 2);
    g_Wph[0][i] = __float2half(Wf[src]);
    g_Wph[1][i] = __float2half(Wb[src]);
}

__global__ void prep_u(const float* __restrict__ Uf, const float* __restrict__ Ub) {
    int i = blockIdx.x * 256 + threadIdx.x;
    if (i >= H_ * G4) return;
    int n = i % G4;
    int k = i / G4;
    int src = k * G4 + (n & 3) * H_ + (n >> 2);
    g_Ut[0][(size_t)n * H_ + k] = __float2half(Uf[src]);
    g_Ut[1][(size_t)n * H_ + k] = __float2half(Ub[src]);
}

__global__ void prep_state() {
    int i = blockIdx.x * 256 + threadIdx.x;
    if (i >= B_ * H_) return;
    g_h[0][0][i] = __half(0.0f); g_h[0][1][i] = __half(0.0f);
    g_h[1][0][i] = __half(0.0f); g_h[1][1][i] = __half(0.0f);
}

// ---------------- input projection GEMM (fp16 in, fp16 out) -----------------
#define PJ_PAD 24

__global__ __launch_bounds__(256) void proj_kernel(const float* __restrict__ bfv,
                                                   const float* __restrict__ bbv) {
    __shared__ __half As[128][PJ_PAD];
    __shared__ __half Bs[128][PJ_PAD];

    const int dir = blockIdx.z;
    const __half* __restrict__ Wp = g_Wph[dir];
    const __half* __restrict__ xh = g_xh;
    const float* __restrict__ bias = dir ? bbv : bfv;
    const int row0 = blockIdx.x * 128;
    const int n0   = blockIdx.y * 128;
    const int tid  = threadIdx.x;
    const int lane = tid & 31;
    const int warp = tid >> 5;
    const int wm = warp & 1;
    const int wn = warp >> 1;

    const uint32_t As_base = (uint32_t)__cvta_generic_to_shared(&As[0][0]);
    const uint32_t Bs_base = (uint32_t)__cvta_generic_to_shared(&Bs[0][0]);
    const int lrow = lane & 15;
    const int lkc  = (lane >> 4) * 8;

    float acc[4][4][4];
    #pragma unroll
    for (int mi = 0; mi < 4; mi++)
        #pragma unroll
        for (int ni = 0; ni < 4; ni++)
            #pragma unroll
            for (int e = 0; e < 4; e++) acc[mi][ni][e] = 0.0f;

    for (int k0 = 0; k0 < D_; k0 += 16) {
        {
            int row = tid >> 1;
            int c8 = (tid & 1) * 8;
            uint4 v = *(const uint4*)(xh + (size_t)(row0 + row) * D_ + k0 + c8);
            *(uint4*)&As[row][c8] = v;
        }
        {
            int row = tid >> 1;
            int c8 = (tid & 1) * 8;
            uint4 v = *(const uint4*)(Wp + (size_t)(n0 + row) * D_ + k0 + c8);
            *(uint4*)&Bs[row][c8] = v;
        }
        __syncthreads();

        uint32_t bfr[4][2];
        #pragma unroll
        for (int np = 0; np < 2; np++) {
            uint32_t b4[4];
            ldsm_x4(b4, Bs_base + (uint32_t)(((wn * 32 + np * 16 + lrow) * PJ_PAD + lkc) * 2));
            bfr[np * 2 + 0][0] = b4[0]; bfr[np * 2 + 1][0] = b4[1];
            bfr[np * 2 + 0][1] = b4[2]; bfr[np * 2 + 1][1] = b4[3];
        }
        #pragma unroll
        for (int mi = 0; mi < 4; mi++) {
            uint32_t af[4];
            ldsm_x4(af, As_base + (uint32_t)(((wm * 64 + mi * 16 + lrow) * PJ_PAD + lkc) * 2));
            #pragma unroll
            for (int ni = 0; ni < 4; ni++)
                mma_f16(acc[mi][ni], af, bfr[ni][0], bfr[ni][1]);
        }
        __syncthreads();
    }

    #pragma unroll
    for (int mi = 0; mi < 4; mi++) {
        #pragma unroll
        for (int ni = 0; ni < 4; ni++) {
            int rl = wm * 64 + mi * 16 + (lane >> 2);
            int cl = wn * 32 + ni * 8 + 2 * (lane & 3);
            #pragma unroll
            for (int p = 0; p < 2; p++) {
                int rr = rl + p * 8;
                int grow = row0 + rr;
                int b = grow >> 10;
                int t = grow & (T_ - 1);
                int n = n0 + cl;
                float v0 = acc[mi][ni][2 * p + 0] + __ldg(&bias[(n & 3) * H_ + (n >> 2)]);
                float v1 = acc[mi][ni][2 * p + 1] + __ldg(&bias[((n + 1) & 3) * H_ + ((n + 1) >> 2)]);
                *(__half2*)&g_xzh[dir][((size_t)t * B_ + b) * G4 + n] =
                    __floats2half2_rn(v0, v1);
            }
        }
    }
}

// ---------------- persistent recurrent kernel (R12 + deferred out stores) ---
#define UT_PAD   776                 // halves per Ut row
#define A_PAD    72                  // halves per A-stage row
#define SMEM_UT_HALVES (NTILE * UT_PAD)
#define SMEM_A_HALVES  (4 * 64 * A_PAD)
#define SMEM_BYTES 118784   // pad to 116KB: forces occupancy 1 -> 1 block/SM

__global__ __launch_bounds__(256, 1) void rnn_persistent(float* __restrict__ out) {
    extern __shared__ char smem_raw[];
    __half* Us = (__half*)smem_raw;                              // [48][UT_PAD]
    __half* Ah = (__half*)(smem_raw + SMEM_UT_HALVES * 2);       // 4 stages [64][A_PAD]

    const int dir = blockIdx.y;
    const int n0  = blockIdx.x * NTILE;
    const int tid = threadIdx.x;
    const int lane = tid & 31;
    const int warp = tid >> 5;
    const int wm = warp & 3;     // 4 m-groups (batch rows)
    const int wn = warp >> 2;    // 2 n-groups (24 z-cols each)

    const __half* __restrict__ xzd = g_xzh[dir];

    // ---- load Ut tile once ----
    {
        const __half* src = g_Ut[dir] + (size_t)n0 * H_;
        for (int idx = tid; idx < NTILE * 96; idx += 256) {
            int n = idx / 96, ch = idx % 96;
            uint4 v = *(const uint4*)(src + (size_t)n * H_ + ch * 8);
            *(uint4*)(Us + n * UT_PAD + ch * 8) = v;
        }
    }
    __syncthreads();

    // cp.async geometry (64 rows x 64 halves per stage)
    const int ar   = tid >> 2;
    const int ac16 = (tid & 3) * 16;
    const uint32_t a_dst_base =
        (uint32_t)__cvta_generic_to_shared(Ah + ar * A_PAD + ac16);
    const uint32_t a_stage_stride = 64 * A_PAD * 2;

    // ldmatrix geometry
    const int lrow = lane & 15;
    const int lkc  = (lane >> 4) * 8;
    const int l15  = lane & 15;
    const uint32_t Ah_base = (uint32_t)__cvta_generic_to_shared(Ah);
    const uint32_t Us_base = (uint32_t)__cvta_generic_to_shared(Us);
    const uint32_t a_frag0 = Ah_base + (uint32_t)(((wm * 16 + lrow) * A_PAD + lkc) * 2);
    const uint32_t u4_base = Us_base + (uint32_t)(((wn * 24 + lrow) * UT_PAD + lkc) * 2);
    const uint32_t u2_base = Us_base + (uint32_t)(((wn * 24 + 16 + (l15 & 7)) * UT_PAD
                                                   + (l15 >> 3) * 8) * 2);

    // epilogue geometry
    const int c0 = wn * 24 + 2 * (lane & 3);
    const int jg = (n0 >> 2) + wn * 6 + ((lane & 3) >> 1);
    const bool store_lane = ((lane & 1) == 0);

    float creg[2][3];
    #pragma unroll
    for (int p = 0; p < 2; p++)
        #pragma unroll
        for (int ni = 0; ni < 3; ni++) creg[p][ni] = 0.0f;

    unsigned bar_gen_seen;
    asm volatile("ld.relaxed.gpu.u32 %0, [%1];"
                 : "=r"(bar_gen_seen) : "l"(&g_bar_gen[dir][0]));

    __half2 xzr[2][3];
    {
        const int tt0 = dir ? (T_ - 1) : 0;
        const __half* xb = xzd + (size_t)tt0 * (B_ * G4) + n0 + c0;
        #pragma unroll
        for (int p = 0; p < 2; p++) {
            int b = wm * 16 + (lane >> 2) + 8 * p;
            #pragma unroll
            for (int ni = 0; ni < 3; ni++)
                xzr[p][ni] = __ldcs((const __half2*)(xb + (size_t)b * G4 + ni * 8));
        }
    }

    float hold[2][3];          // deferred out values from previous step
    int   tt_prev = -1;

    for (int t = 0; t < T_; t++) {
        const __half* __restrict__ hp = g_h[dir][t & 1];
        __half* __restrict__ hnext = g_h[dir][(t + 1) & 1];
        const int tt = dir ? (T_ - 1 - t) : t;

        // two independent accumulator banks (even/odd ks) -> 6 chains per warp
        float acc[3][4], acc2[3][4];
        #pragma unroll
        for (int ni = 0; ni < 3; ni++)
            #pragma unroll
            for (int e = 0; e < 4; e++) { acc[ni][e] = 0.0f; acc2[ni][e] = 0.0f; }

        const char* hsrc = (const char*)(hp + (size_t)ar * H_ + ac16);

        #pragma unroll
        for (int s = 0; s < 3; s++) {
            cp_async16(a_dst_base + s * a_stage_stride, hsrc + (size_t)s * 128);
            cp_async16(a_dst_base + s * a_stage_stride + 16, hsrc + (size_t)s * 128 + 16);
            CP_COMMIT();
        }

        // deferred out stores from step t-1: overlap with stage-0 L2 latency
        if (tt_prev >= 0 && store_lane) {
            #pragma unroll
            for (int p = 0; p < 2; p++) {
                int b = wm * 16 + (lane >> 2) + 8 * p;
                #pragma unroll
                for (int ni = 0; ni < 3; ni++)
                    out[((size_t)b * T_ + tt_prev) * OW + dir * H_ + jg + 2 * ni] =
                        hold[p][ni];
            }
        }

        for (int i = 0; i < 12; i++) {     // k64 stages
            CP_WAIT2();
            __syncthreads();
            if (i < 9) {
                uint32_t d = a_dst_base + ((i + 3) & 3) * a_stage_stride;
                const char* s = hsrc + (size_t)(i + 3) * 128;
                cp_async16(d, s);
                cp_async16(d + 16, s + 16);
            }
            CP_COMMIT();

            const uint32_t a_st = a_frag0 + (uint32_t)(i & 3) * a_stage_stride;
            const uint32_t kb   = (uint32_t)(i * 128);   // i*64 halves in bytes
            #pragma unroll
            for (int ks = 0; ks < 4; ks++) {
                uint32_t b4[4], bx[2], af[4];
                ldsm_x4(b4, u4_base + kb + ks * 32);
                ldsm_x2(bx, u2_base + kb + ks * 32);
                ldsm_x4(af, a_st + ks * 32);
                float (*A)[4] = (ks & 1) ? acc2 : acc;
                mma_f16(A[0], af, b4[0], b4[2]);
                mma_f16(A[1], af, b4[1], b4[3]);
                mma_f16(A[2], af, bx[0], bx[1]);
            }
        }

        // merge accumulator banks
        #pragma unroll
        for (int ni = 0; ni < 3; ni++)
            #pragma unroll
            for (int e = 0; e < 4; e++) acc[ni][e] += acc2[ni][e];

        // ---- epilogue: gates + h-state store (critical); out deferred ----
        #pragma unroll
        for (int p = 0; p < 2; p++) {
            int b = wm * 16 + (lane >> 2) + 8 * p;
            #pragma unroll
            for (int ni = 0; ni < 3; ni++) {
                float2 xf = __half22float2(xzr[p][ni]);
                float a0 = acc[ni][2 * p + 0] + xf.x;
                float a1 = acc[ni][2 * p + 1] + xf.y;
                float b0 = __shfl_xor_sync(0xffffffffu, a0, 1);
                float b1 = __shfl_xor_sync(0xffffffffu, a1, 1);
                bool oddl = lane & 1;
                float zi = oddl ? b0 : a0;
                float zf = oddl ? b1 : a1;
                float zg = oddl ? a0 : b0;
                float zo = oddl ? a1 : b1;

                float ig = sigm_(zi);
                float fg = sigm_(zf);
                float og = sigm_(zo);
                float c = fg * creg[p][ni] + ig * tanhf_(zg);
                creg[p][ni] = c;
                float h = og * tanhf_(c);
                hold[p][ni] = h;

                if (store_lane)
                    hnext[b * H_ + jg + 2 * ni] = __float2half(h);
            }
        }
        tt_prev = tt;

        // xz prefetch for t+1
        if (t + 1 < T_) {
            const int tn = dir ? (T_ - 2 - t) : (t + 1);
            const __half* xb = xzd + (size_t)tn * (B_ * G4) + n0 + c0;
            #pragma unroll
            for (int p = 0; p < 2; p++) {
                int b = wm * 16 + (lane >> 2) + 8 * p;
                #pragma unroll
                for (int ni = 0; ni < 3; ni++)
                    xzr[p][ni] = __ldcs((const __half2*)(xb + (size_t)b * G4 + ni * 8));
            }
        }

        // ---- per-direction flat grid barrier (acq_rel atomics) ----
        __syncthreads();
        if (tid == 0) {
            unsigned old;
            asm volatile("atom.acq_rel.gpu.add.u32 %0, [%1], 1;"
                         : "=r"(old) : "l"(&g_bar_cnt[dir][0]) : "memory");
            if (old == NBD - 1) {
                asm volatile("st.relaxed.gpu.u32 [%0], 0;"
                             :: "l"(&g_bar_cnt[dir][0]) : "memory");
                asm volatile("st.release.gpu.u32 [%0], %1;"
                             :: "l"(&g_bar_gen[dir][0]), "r"(bar_gen_seen + 1) : "memory");
            } else {
                unsigned g;
                do {
                    asm volatile("ld.acquire.gpu.u32 %0, [%1];"
                                 : "=r"(g) : "l"(&g_bar_gen[dir][0]) : "memory");
                } while (g == bar_gen_seen);
            }
        }
        bar_gen_seen++;
        __syncthreads();
    }

    // flush final step's out values
    if (store_lane) {
        #pragma unroll
        for (int p = 0; p < 2; p++) {
            int b = wm * 16 + (lane >> 2) + 8 * p;
            #pragma unroll
            for (int ni = 0; ni < 3; ni++)
                out[((size_t)b * T_ + tt_prev) * OW + dir * H_ + jg + 2 * ni] =
                    hold[p][ni];
        }
    }
}

// ---------------- launch ----------------------------------------------------
extern "C" void kernel_launch(void* const* d_in, const int* in_sizes, int n_in,
                              void* d_out, int out_size) {
    (void)in_sizes; (void)n_in; (void)out_size;
    const float* x  = (const float*)d_in[0];
    const float* Wf = (const float*)d_in[1];
    const float* Uf = (const float*)d_in[2];
    const float* bf = (const float*)d_in[3];
    const float* Wb = (const float*)d_in[4];
    const float* Ub = (const float*)d_in[5];
    const float* bb = (const float*)d_in[6];
    float* out = (float*)d_out;

    cudaFuncSetAttribute(rnn_persistent,
                         cudaFuncAttributeMaxDynamicSharedMemorySize, SMEM_BYTES);

    prep_x<<<(int)(((size_t)B_ * T_ * D_ + 255) / 256), 256>>>(x);
    prep_w<<<(G4 * D_ + 255) / 256, 256>>>(Wf, Wb);
    prep_u<<<(H_ * G4 + 255) / 256, 256>>>(Uf, Ub);
    prep_state<<<(B_ * H_ + 255) / 256, 256>>>();

    proj_kernel<<<dim3(512, 24, 2), 256>>>(bf, bb);

    rnn_persistent<<<dim3(NBD, 2), 256, SMEM_BYTES>>>(out);
}

// round 16
// speedup vs baseline: 1.0652x; 1.0428x over previous
#include <cuda_runtime.h>
#include <cuda_fp16.h>
#include <cstdint>
#include <cmath>

#define B_ 64
#define T_ 1024
#define D_ 512
#define H_ 768
#define G4 3072   // 4*H
#define OW 1536   // 2*H
#define NBD 64    // column blocks per direction
#define NTILE 48  // z-columns per block

// ---------------- scratch (device globals) ----------------------------------
__device__ __half   g_xzh[2][(size_t)T_ * B_ * G4];  // gate-permuted input proj, fp16
__device__ __half   g_xh[(size_t)B_ * T_ * D_];      // x converted to fp16
__device__ __half   g_Wph[2][(size_t)G4 * D_];       // permuted W, transposed [n][k]
__device__ __half   g_Ut[2][(size_t)G4 * H_];        // permuted U, transposed [n][k]
__device__ __half   g_h[2][2][B_ * H_];              // [dir][phase], fp16
__device__ unsigned g_bar_cnt[2][32];                // padded: one line per dir
__device__ unsigned g_bar_gen[2][32];

// ---------------- helpers --------------------------------------------------
__device__ __forceinline__ void mma_f16(float* c, const uint32_t* a,
                                        uint32_t b0, uint32_t b1) {
    asm volatile(
        "mma.sync.aligned.m16n8k16.row.col.f32.f16.f16.f32 "
        "{%0,%1,%2,%3}, {%4,%5,%6,%7}, {%8,%9}, {%0,%1,%2,%3};"
        : "+f"(c[0]), "+f"(c[1]), "+f"(c[2]), "+f"(c[3])
        : "r"(a[0]), "r"(a[1]), "r"(a[2]), "r"(a[3]), "r"(b0), "r"(b1));
}
__device__ __forceinline__ void ldsm_x4(uint32_t* r, uint32_t saddr) {
    asm volatile("ldmatrix.sync.aligned.m8n8.x4.shared.b16 {%0,%1,%2,%3}, [%4];"
        : "=r"(r[0]), "=r"(r[1]), "=r"(r[2]), "=r"(r[3]) : "r"(saddr));
}
__device__ __forceinline__ void ldsm_x2(uint32_t* r, uint32_t saddr) {
    asm volatile("ldmatrix.sync.aligned.m8n8.x2.shared.b16 {%0,%1}, [%2];"
        : "=r"(r[0]), "=r"(r[1]) : "r"(saddr));
}
__device__ __forceinline__ void cp_async16(uint32_t smem_u32, const void* gptr) {
    asm volatile("cp.async.cg.shared.global [%0], [%1], 16;"
                 :: "r"(smem_u32), "l"(gptr));
}
#define CP_COMMIT() asm volatile("cp.async.commit_group;")
#define CP_WAIT2()  asm volatile("cp.async.wait_group 2;")

__device__ __forceinline__ float tanhf_(float x) {
    float r; asm("tanh.approx.f32 %0, %1;" : "=f"(r) : "f"(x)); return r;
}
__device__ __forceinline__ float sigm_(float x) {
    return fmaf(0.5f, tanhf_(0.5f * x), 0.5f);
}

// ---------------- prep kernels ---------------------------------------------
__global__ void prep_x(const float* __restrict__ x) {
    size_t i = (size_t)blockIdx.x * 256 + threadIdx.x;
    if (i >= (size_t)B_ * T_ * D_) return;
    g_xh[i] = __float2half(x[i]);
}

__global__ void prep_w(const float* __restrict__ Wf, const float* __restrict__ Wb) {
    int i = blockIdx.x * 256 + threadIdx.x;
    if (i >= G4 * D_) return;
    int n = i / D_;
    int k = i % D_;
    int src = k * G4 + (n & 3) * H_ + (n >> 2);
    g_Wph[0][i] = __float2half(Wf[src]);
    g_Wph[1][i] = __float2half(Wb[src]);
}

__global__ void prep_u(const float* __restrict__ Uf, const float* __restrict__ Ub) {
    int i = blockIdx.x * 256 + threadIdx.x;
    if (i >= H_ * G4) return;
    int n = i % G4;
    int k = i / G4;
    int src = k * G4 + (n & 3) * H_ + (n >> 2);
    g_Ut[0][(size_t)n * H_ + k] = __float2half(Uf[src]);
    g_Ut[1][(size_t)n * H_ + k] = __float2half(Ub[src]);
}

__global__ void prep_state() {
    int i = blockIdx.x * 256 + threadIdx.x;
    if (i >= B_ * H_) return;
    g_h[0][0][i] = __half(0.0f); g_h[0][1][i] = __half(0.0f);
    g_h[1][0][i] = __half(0.0f); g_h[1][1][i] = __half(0.0f);
}

// ---------------- input projection GEMM: 4-stage cp.async pipeline ----------
// BM=128, BN=128, BK=32, 16 pipelined k-iters, one __syncthreads per iter.
#define PJS 40                              // halves per stage row (80B stride)
#define PJ_STAGE_H (128 * PJS)              // halves per matrix per stage
#define PJ_SMEM_BYTES (4 * 2 * PJ_STAGE_H * 2)   // 4 stages x (A+B) x 2B = 81920

__global__ __launch_bounds__(256) void proj_kernel(const float* __restrict__ bfv,
                                                   const float* __restrict__ bbv) {
    extern __shared__ __half pjs[];
    __half* As = pjs;                        // [4][128][PJS]
    __half* Bs = pjs + 4 * PJ_STAGE_H;       // [4][128][PJS]

    const int dir = blockIdx.z;
    const __half* __restrict__ Wp = g_Wph[dir];
    const __half* __restrict__ xh = g_xh;
    const float* __restrict__ bias = dir ? bbv : bfv;
    const int row0 = blockIdx.x * 128;
    const int n0   = blockIdx.y * 128;
    const int tid  = threadIdx.x;
    const int lane = tid & 31;
    const int warp = tid >> 5;
    const int wm = warp & 1;
    const int wn = warp >> 1;

    // load geometry: 2 threads/row, each copies 32 contiguous bytes (2x cp16)
    const int lr  = tid >> 1;                // 0..127
    const int lc  = (tid & 1) * 16;          // halves offset within 32-half row
    const __half* ga = xh + (size_t)(row0 + lr) * D_ + lc;
    const __half* gb = Wp + (size_t)(n0 + lr) * D_ + lc;
    const uint32_t sa = (uint32_t)__cvta_generic_to_shared(As + lr * PJS + lc);
    const uint32_t sb = (uint32_t)__cvta_generic_to_shared(Bs + lr * PJS + lc);
    const uint32_t stg = PJ_STAGE_H * 2;     // stage stride bytes

    // ldmatrix geometry
    const uint32_t As_base = (uint32_t)__cvta_generic_to_shared(As);
    const uint32_t Bs_base = (uint32_t)__cvta_generic_to_shared(Bs);
    const int lrow = lane & 15;
    const int lkc  = (lane >> 4) * 8;

    float acc[4][4][4];
    #pragma unroll
    for (int mi = 0; mi < 4; mi++)
        #pragma unroll
        for (int ni = 0; ni < 4; ni++)
            #pragma unroll
            for (int e = 0; e < 4; e++) acc[mi][ni][e] = 0.0f;

    auto load_stage = [&](int i) {           // k0 = i*32
        int s = i & 3;
        const __half* a = ga + i * 32;
        const __half* b = gb + i * 32;
        cp_async16(sa + s * stg,      a);        // halves lc..lc+7
        cp_async16(sa + s * stg + 16, a + 8);    // halves lc+8..lc+15
        cp_async16(sb + s * stg,      b);
        cp_async16(sb + s * stg + 16, b + 8);
        CP_COMMIT();
    };

    load_stage(0); load_stage(1); load_stage(2);

    for (int i = 0; i < 16; i++) {           // D_/32 iters
        CP_WAIT2();
        __syncthreads();
        if (i < 13) load_stage(i + 3);
        else        CP_COMMIT();

        const uint32_t a_st = As_base + (uint32_t)(i & 3) * stg;
        const uint32_t b_st = Bs_base + (uint32_t)(i & 3) * stg;
        #pragma unroll
        for (int kk = 0; kk < 32; kk += 16) {
            uint32_t bfr[4][2];
            #pragma unroll
            for (int np = 0; np < 2; np++) {
                uint32_t b4[4];
                ldsm_x4(b4, b_st + (uint32_t)(((wn * 32 + np * 16 + lrow) * PJS + kk + lkc) * 2));
                bfr[np * 2 + 0][0] = b4[0]; bfr[np * 2 + 1][0] = b4[1];
                bfr[np * 2 + 0][1] = b4[2]; bfr[np * 2 + 1][1] = b4[3];
            }
            #pragma unroll
            for (int mi = 0; mi < 4; mi++) {
                uint32_t af[4];
                ldsm_x4(af, a_st + (uint32_t)(((wm * 64 + mi * 16 + lrow) * PJS + kk + lkc) * 2));
                #pragma unroll
                for (int ni = 0; ni < 4; ni++)
                    mma_f16(acc[mi][ni], af, bfr[ni][0], bfr[ni][1]);
            }
        }
    }

    #pragma unroll
    for (int mi = 0; mi < 4; mi++) {
        #pragma unroll
        for (int ni = 0; ni < 4; ni++) {
            int rl = wm * 64 + mi * 16 + (lane >> 2);
            int cl = wn * 32 + ni * 8 + 2 * (lane & 3);
            #pragma unroll
            for (int p = 0; p < 2; p++) {
                int rr = rl + p * 8;
                int grow = row0 + rr;
                int b = grow >> 10;
                int t = grow & (T_ - 1);
                int n = n0 + cl;
                float v0 = acc[mi][ni][2 * p + 0] + __ldg(&bias[(n & 3) * H_ + (n >> 2)]);
                float v1 = acc[mi][ni][2 * p + 1] + __ldg(&bias[((n + 1) & 3) * H_ + ((n + 1) >> 2)]);
                *(__half2*)&g_xzh[dir][((size_t)t * B_ + b) * G4 + n] =
                    __floats2half2_rn(v0, v1);
            }
        }
    }
}

// ---------------- persistent recurrent kernel (R12 verbatim, 9037us best) ---
#define UT_PAD   776                 // halves per Ut row
#define A_PAD    72                  // halves per A-stage row
#define SMEM_UT_HALVES (NTILE * UT_PAD)
#define SMEM_A_HALVES  (4 * 64 * A_PAD)
#define SMEM_BYTES 118784   // pad to 116KB: forces occupancy 1 -> 1 block/SM

__global__ __launch_bounds__(256, 1) void rnn_persistent(float* __restrict__ out) {
    extern __shared__ char smem_raw[];
    __half* Us = (__half*)smem_raw;                              // [48][UT_PAD]
    __half* Ah = (__half*)(smem_raw + SMEM_UT_HALVES * 2);       // 4 stages [64][A_PAD]

    const int dir = blockIdx.y;
    const int n0  = blockIdx.x * NTILE;
    const int tid = threadIdx.x;
    const int lane = tid & 31;
    const int warp = tid >> 5;
    const int wm = warp & 3;     // 4 m-groups (batch rows)
    const int wn = warp >> 2;    // 2 n-groups (24 z-cols each)

    const __half* __restrict__ xzd = g_xzh[dir];

    // ---- load Ut tile once ----
    {
        const __half* src = g_Ut[dir] + (size_t)n0 * H_;
        for (int idx = tid; idx < NTILE * 96; idx += 256) {
            int n = idx / 96, ch = idx % 96;
            uint4 v = *(const uint4*)(src + (size_t)n * H_ + ch * 8);
            *(uint4*)(Us + n * UT_PAD + ch * 8) = v;
        }
    }
    __syncthreads();

    // cp.async geometry (64 rows x 64 halves per stage)
    const int ar   = tid >> 2;
    const int ac16 = (tid & 3) * 16;
    const uint32_t a_dst_base =
        (uint32_t)__cvta_generic_to_shared(Ah + ar * A_PAD + ac16);
    const uint32_t a_stage_stride = 64 * A_PAD * 2;

    // ldmatrix geometry
    const int lrow = lane & 15;
    const int lkc  = (lane >> 4) * 8;
    const int l15  = lane & 15;
    const uint32_t Ah_base = (uint32_t)__cvta_generic_to_shared(Ah);
    const uint32_t Us_base = (uint32_t)__cvta_generic_to_shared(Us);
    const uint32_t a_frag0 = Ah_base + (uint32_t)(((wm * 16 + lrow) * A_PAD + lkc) * 2);
    const uint32_t u4_base = Us_base + (uint32_t)(((wn * 24 + lrow) * UT_PAD + lkc) * 2);
    const uint32_t u2_base = Us_base + (uint32_t)(((wn * 24 + 16 + (l15 & 7)) * UT_PAD
                                                   + (l15 >> 3) * 8) * 2);

    // epilogue geometry
    const int c0 = wn * 24 + 2 * (lane & 3);
    const int jg = (n0 >> 2) + wn * 6 + ((lane & 3) >> 1);
    const bool store_lane = ((lane & 1) == 0);

    float creg[2][3];
    #pragma unroll
    for (int p = 0; p < 2; p++)
        #pragma unroll
        for (int ni = 0; ni < 3; ni++) creg[p][ni] = 0.0f;

    unsigned bar_gen_seen;
    asm volatile("ld.relaxed.gpu.u32 %0, [%1];"
                 : "=r"(bar_gen_seen) : "l"(&g_bar_gen[dir][0]));

    __half2 xzr[2][3];
    {
        const int tt0 = dir ? (T_ - 1) : 0;
        const __half* xb = xzd + (size_t)tt0 * (B_ * G4) + n0 + c0;
        #pragma unroll
        for (int p = 0; p < 2; p++) {
            int b = wm * 16 + (lane >> 2) + 8 * p;
            #pragma unroll
            for (int ni = 0; ni < 3; ni++)
                xzr[p][ni] = __ldcs((const __half2*)(xb + (size_t)b * G4 + ni * 8));
        }
    }

    for (int t = 0; t < T_; t++) {
        const __half* __restrict__ hp = g_h[dir][t & 1];
        __half* __restrict__ hnext = g_h[dir][(t + 1) & 1];
        const int tt = dir ? (T_ - 1 - t) : t;

        // two independent accumulator banks (even/odd ks) -> 6 chains per warp
        float acc[3][4], acc2[3][4];
        #pragma unroll
        for (int ni = 0; ni < 3; ni++)
            #pragma unroll
            for (int e = 0; e < 4; e++) { acc[ni][e] = 0.0f; acc2[ni][e] = 0.0f; }

        const char* hsrc = (const char*)(hp + (size_t)ar * H_ + ac16);

        #pragma unroll
        for (int s = 0; s < 3; s++) {
            cp_async16(a_dst_base + s * a_stage_stride, hsrc + (size_t)s * 128);
            cp_async16(a_dst_base + s * a_stage_stride + 16, hsrc + (size_t)s * 128 + 16);
            CP_COMMIT();
        }

        for (int i = 0; i < 12; i++) {     // k64 stages
            CP_WAIT2();
            __syncthreads();
            if (i < 9) {
                uint32_t d = a_dst_base + ((i + 3) & 3) * a_stage_stride;
                const char* s = hsrc + (size_t)(i + 3) * 128;
                cp_async16(d, s);
                cp_async16(d + 16, s + 16);
            }
            CP_COMMIT();

            const uint32_t a_st = a_frag0 + (uint32_t)(i & 3) * a_stage_stride;
            const uint32_t kb   = (uint32_t)(i * 128);   // i*64 halves in bytes
            #pragma unroll
            for (int ks = 0; ks < 4; ks++) {
                uint32_t b4[4], bx[2], af[4];
                ldsm_x4(b4, u4_base + kb + ks * 32);
                ldsm_x2(bx, u2_base + kb + ks * 32);
                ldsm_x4(af, a_st + ks * 32);
                float (*A)[4] = (ks & 1) ? acc2 : acc;
                mma_f16(A[0], af, b4[0], b4[2]);
                mma_f16(A[1], af, b4[1], b4[3]);
                mma_f16(A[2], af, bx[0], bx[1]);
            }
        }

        // merge accumulator banks
        #pragma unroll
        for (int ni = 0; ni < 3; ni++)
            #pragma unroll
            for (int e = 0; e < 4; e++) acc[ni][e] += acc2[ni][e];

        // ---- epilogue in fragment layout ----
        #pragma unroll
        for (int p = 0; p < 2; p++) {
            int b = wm * 16 + (lane >> 2) + 8 * p;
            #pragma unroll
            for (int ni = 0; ni < 3; ni++) {
                float2 xf = __half22float2(xzr[p][ni]);
                float a0 = acc[ni][2 * p + 0] + xf.x;
                float a1 = acc[ni][2 * p + 1] + xf.y;
                float b0 = __shfl_xor_sync(0xffffffffu, a0, 1);
                float b1 = __shfl_xor_sync(0xffffffffu, a1, 1);
                bool oddl = lane & 1;
                float zi = oddl ? b0 : a0;
                float zf = oddl ? b1 : a1;
                float zg = oddl ? a0 : b0;
                float zo = oddl ? a1 : b1;

                float ig = sigm_(zi);
                float fg = sigm_(zf);
                float og = sigm_(zo);
                float c = fg * creg[p][ni] + ig * tanhf_(zg);
                creg[p][ni] = c;
                float h = og * tanhf_(c);

                if (store_lane) {
                    int j = jg + 2 * ni;
                    hnext[b * H_ + j] = __float2half(h);
                    out[((size_t)b * T_ + tt) * OW + dir * H_ + j] = h;
                }
            }
        }

        // xz prefetch for t+1
        if (t + 1 < T_) {
            const int tn = dir ? (T_ - 2 - t) : (t + 1);
            const __half* xb = xzd + (size_t)tn * (B_ * G4) + n0 + c0;
            #pragma unroll
            for (int p = 0; p < 2; p++) {
                int b = wm * 16 + (lane >> 2) + 8 * p;
                #pragma unroll
                for (int ni = 0; ni < 3; ni++)
                    xzr[p][ni] = __ldcs((const __half2*)(xb + (size_t)b * G4 + ni * 8));
            }
        }

        // ---- per-direction flat grid barrier (acq_rel atomics) ----
        __syncthreads();
        if (tid == 0) {
            unsigned old;
            asm volatile("atom.acq_rel.gpu.add.u32 %0, [%1], 1;"
                         : "=r"(old) : "l"(&g_bar_cnt[dir][0]) : "memory");
            if (old == NBD - 1) {
                asm volatile("st.relaxed.gpu.u32 [%0], 0;"
                             :: "l"(&g_bar_cnt[dir][0]) : "memory");
                asm volatile("st.release.gpu.u32 [%0], %1;"
                             :: "l"(&g_bar_gen[dir][0]), "r"(bar_gen_seen + 1) : "memory");
            } else {
                unsigned g;
                do {
                    asm volatile("ld.acquire.gpu.u32 %0, [%1];"
                                 : "=r"(g) : "l"(&g_bar_gen[dir][0]) : "memory");
                } while (g == bar_gen_seen);
            }
        }
        bar_gen_seen++;
        __syncthreads();
    }
}

// ---------------- launch ----------------------------------------------------
extern "C" void kernel_launch(void* const* d_in, const int* in_sizes, int n_in,
                              void* d_out, int out_size) {
    (void)in_sizes; (void)n_in; (void)out_size;
    const float* x  = (const float*)d_in[0];
    const float* Wf = (const float*)d_in[1];
    const float* Uf = (const float*)d_in[2];
    const float* bf = (const float*)d_in[3];
    const float* Wb = (const float*)d_in[4];
    const float* Ub = (const float*)d_in[5];
    const float* bb = (const float*)d_in[6];
    float* out = (float*)d_out;

    cudaFuncSetAttribute(rnn_persistent,
                         cudaFuncAttributeMaxDynamicSharedMemorySize, SMEM_BYTES);
    cudaFuncSetAttribute(proj_kernel,
                         cudaFuncAttributeMaxDynamicSharedMemorySize, PJ_SMEM_BYTES);

    prep_x<<<(int)(((size_t)B_ * T_ * D_ + 255) / 256), 256>>>(x);
    prep_w<<<(G4 * D_ + 255) / 256, 256>>>(Wf, Wb);
    prep_u<<<(H_ * G4 + 255) / 256, 256>>>(Uf, Ub);
    prep_state<<<(B_ * H_ + 255) / 256, 256>>>();

    proj_kernel<<<dim3(512, 24, 2), 256, PJ_SMEM_BYTES>>>(bf, bb);

    rnn_persistent<<<dim3(NBD, 2), 256, SMEM_BYTES>>>(out);
}